// round 2
// baseline (speedup 1.0000x reference)
#include <cuda_runtime.h>

#define NTOT 32768
#define THREADS 512
#define SBUF 33792            // 32768 + 32768/32 padding
#define SMEM_BYTES ((SBUF + 64) * 4)

// db4 lowpass taps
#define LP0 (-0.010597401784997278f)
#define LP1 ( 0.032883011666982945f)
#define LP2 ( 0.030841381835986965f)
#define LP3 (-0.18703481171888114f)
#define LP4 (-0.02798376941698385f)
#define LP5 ( 0.6308807679295904f)
#define LP6 ( 0.7148465705525415f)
#define LP7 ( 0.23037781330885523f)
// hp[t] = lp[7-t] * (-1)^t
#define HP0 ( LP7)
#define HP1 (-LP6)
#define HP2 ( LP5)
#define HP3 (-LP4)
#define HP4 ( LP3)
#define HP5 (-LP2)
#define HP6 ( LP1)
#define HP7 (-LP0)

__device__ __forceinline__ int sw(int i) { return i + (i >> 5); }

// gate = sigmoid(10(y-b)) + sigmoid(-10(y+b))
//      = (2E + P + E*E*P) / ((1+E*P)*(E+P)),  E = e^{-10y}, P = e^{10b}
__device__ __forceinline__ float actfn(float y, float P) {
    float a  = fminf(41.0f, fmaxf(-41.0f, -10.0f * y));
    float E  = __expf(a);
    float EP = E * P;
    float num = fmaf(EP, E, fmaf(2.0f, E, P));
    float den = (1.0f + EP) * (E + P);
    return y * __fdividef(num, den);
}

__global__ void __launch_bounds__(THREADS, 1)
wpt_kernel(const float* __restrict__ x, float* __restrict__ out,
           const float* __restrict__ b1, const float* __restrict__ b2,
           const float* __restrict__ b3, const float* __restrict__ b4,
           const float* __restrict__ b5)
{
    extern __shared__ float S[];
    float* B = S + SBUF;      // 62 biases
    const int tid = threadIdx.x;
    const int row = blockIdx.x;

    // biases -> smem: offsets 0,2,6,14,30
    if (tid < 2)  B[0  + tid] = b1[tid];
    if (tid < 4)  B[2  + tid] = b2[tid];
    if (tid < 8)  B[6  + tid] = b3[tid];
    if (tid < 16) B[14 + tid] = b4[tid];
    if (tid < 32) B[30 + tid] = b5[tid];

    // load x row into swizzled smem
    const float4* x4 = (const float4*)(x + (size_t)row * NTOT);
    #pragma unroll
    for (int i = 0; i < NTOT / 4 / THREADS; ++i) {
        int idx = tid + i * THREADS;
        float4 v = x4[idx];
        int p = 4 * idx;
        S[sw(p + 0)] = v.x;
        S[sw(p + 1)] = v.y;
        S[sw(p + 2)] = v.z;
        S[sw(p + 3)] = v.w;
    }
    __syncthreads();

    // ---------------- 5 analysis levels (in-place) ----------------
    #pragma unroll 1
    for (int li = 0; li < 5; ++li) {
        const int Nl = NTOT >> li;       // input channel length
        const int M  = Nl >> 1;          // output channel length
        const int pos0 = tid << 5;       // 32 output positions per thread
        const int c  = pos0 >> (14 - li);
        const int m0 = pos0 & (M - 1);
        const int base = c * Nl;

        // stage input window [2*m0-3, 2*m0+66] into registers
        float xs[70];
        #pragma unroll
        for (int j = 0; j < 70; ++j) {
            int idx = 2 * m0 - 3 + j;
            float v = 0.0f;
            if (idx >= 0 && idx < Nl) v = S[sw(base + idx)];
            xs[j] = v;
        }
        const int  bo    = (2 << li) - 2;
        const bool ceven = ((c & 1) == 0);
        const float PA = __expf(10.0f * B[bo + 2 * c]);      // out ch 2c
        const float PB = __expf(10.0f * B[bo + 2 * c + 1]);  // out ch 2c+1
        __syncthreads();

        #pragma unroll
        for (int k = 0; k < 32; ++k) {
            float lpv =
                fmaf(xs[2*k+0], LP0, fmaf(xs[2*k+1], LP1,
                fmaf(xs[2*k+2], LP2, fmaf(xs[2*k+3], LP3,
                fmaf(xs[2*k+4], LP4, fmaf(xs[2*k+5], LP5,
                fmaf(xs[2*k+6], LP6, xs[2*k+7] * LP7)))))));
            float hpv =
                fmaf(xs[2*k+0], HP0, fmaf(xs[2*k+1], HP1,
                fmaf(xs[2*k+2], HP2, fmaf(xs[2*k+3], HP3,
                fmaf(xs[2*k+4], HP4, fmaf(xs[2*k+5], HP5,
                fmaf(xs[2*k+6], HP6, xs[2*k+7] * HP7)))))));
            float vA = ceven ? lpv : hpv;   // out channel 2c
            float vB = ceven ? hpv : lpv;   // out channel 2c+1
            S[sw(base + m0 + k)]     = actfn(vA, PA);
            S[sw(base + M + m0 + k)] = actfn(vB, PB);
        }
        __syncthreads();
    }

    // ---------------- 5 synthesis levels (in-place) ----------------
    #pragma unroll 1
    for (int li = 4; li >= 0; --li) {
        const int M   = NTOT >> (li + 1); // input channel length; output 2M
        const int n0t = tid << 6;         // 64 outputs per thread
        const int c   = n0t >> (15 - li);
        const int n0  = n0t & (2 * M - 1);
        const int m0  = n0 >> 1;
        const bool ceven = ((c & 1) == 0);
        // channel carrying the lowpass row of K, and the highpass one
        const int baseL = (2 * c + (ceven ? 0 : 1)) * M;
        const int baseH = (2 * c + (ceven ? 1 : 0)) * M;

        float yl[36], yh[36];
        #pragma unroll
        for (int j = 0; j < 36; ++j) {
            int m = m0 - 2 + j;
            bool ok = (m >= 0) && (m < M);
            yl[j] = ok ? S[sw(baseL + m)] : 0.0f;
            yh[j] = ok ? S[sw(baseH + m)] : 0.0f;
        }
        __syncthreads();

        const int ob = 2 * c * M + n0;
        #pragma unroll
        for (int u = 0; u < 32; ++u) {
            // even output n0+2u: taps tau = 1,3,5,7 at stage idx u+3,u+2,u+1,u
            float e =
                fmaf(yl[u+3], LP1, fmaf(yl[u+2], LP3,
                fmaf(yl[u+1], LP5, fmaf(yl[u+0], LP7,
                fmaf(yh[u+3], HP1, fmaf(yh[u+2], HP3,
                fmaf(yh[u+1], HP5, yh[u+0] * HP7)))))));
            // odd output n0+2u+1: taps tau = 0,2,4,6 at stage idx u+4..u+1
            float o =
                fmaf(yl[u+4], LP0, fmaf(yl[u+3], LP2,
                fmaf(yl[u+2], LP4, fmaf(yl[u+1], LP6,
                fmaf(yh[u+4], HP0, fmaf(yh[u+3], HP2,
                fmaf(yh[u+2], HP4, yh[u+1] * HP6)))))));
            S[sw(ob + 2*u)]     = e;
            S[sw(ob + 2*u + 1)] = o;
        }
        __syncthreads();
    }

    // store result row
    float4* o4 = (float4*)(out + (size_t)row * NTOT);
    #pragma unroll
    for (int i = 0; i < NTOT / 4 / THREADS; ++i) {
        int idx = tid + i * THREADS;
        int p = 4 * idx;
        float4 v;
        v.x = S[sw(p + 0)];
        v.y = S[sw(p + 1)];
        v.z = S[sw(p + 2)];
        v.w = S[sw(p + 3)];
        o4[idx] = v;
    }
}

extern "C" void kernel_launch(void* const* d_in, const int* in_sizes, int n_in,
                              void* d_out, int out_size)
{
    // locate x (the 128*32768 input) and the bias vectors (sizes 2,4,8,16,32;
    // scan from the END since k1/k2 have colliding sizes 16/32 earlier in order)
    const float* x = (const float*)d_in[0];
    for (int i = 0; i < n_in; ++i)
        if (in_sizes[i] == 128 * NTOT) { x = (const float*)d_in[i]; break; }

    const float* bs[5] = {nullptr, nullptr, nullptr, nullptr, nullptr};
    for (int i = n_in - 1; i >= 0; --i) {
        int s = in_sizes[i];
        for (int l = 0; l < 5; ++l) {
            if (s == (2 << l) && bs[l] == nullptr) {
                bs[l] = (const float*)d_in[i];
                break;
            }
        }
    }

    cudaFuncSetAttribute(wpt_kernel, cudaFuncAttributeMaxDynamicSharedMemorySize,
                         SMEM_BYTES);

    int rows = out_size / NTOT;
    wpt_kernel<<<rows, THREADS, SMEM_BYTES>>>(
        x, (float*)d_out, bs[0], bs[1], bs[2], bs[3], bs[4]);
}

// round 5
// speedup vs baseline: 1.4674x; 1.4674x over previous
#include <cuda_runtime.h>

#define NTOT 32768
#define THREADS 512
#define SBUF 33808            // >= sw(NTOT+4) with margin
#define GUARD 8
#define SMEM_FLOATS (GUARD + SBUF + GUARD + 64)
#define SMEM_BYTES (SMEM_FLOATS * 4)

// db4 lowpass taps
#define LP0 (-0.010597401784997278f)
#define LP1 ( 0.032883011666982945f)
#define LP2 ( 0.030841381835986965f)
#define LP3 (-0.18703481171888114f)
#define LP4 (-0.02798376941698385f)
#define LP5 ( 0.6308807679295904f)
#define LP6 ( 0.7148465705525415f)
#define LP7 ( 0.23037781330885523f)
// hp[t] = lp[7-t] * (-1)^t
#define HP0 ( LP7)
#define HP1 (-LP6)
#define HP2 ( LP5)
#define HP3 (-LP4)
#define HP4 ( LP3)
#define HP5 (-LP2)
#define HP6 ( LP1)
#define HP7 (-LP0)

// gate(y,b) = sigmoid(10(y-b)) + sigmoid(-10(y+b)) is even in y.
// With z=|y|, E=e^{-10z} in (0,1], P=e^{10b} in [1,e]:
// gate = (2E + P + E*E*P) / ((1+E*P)*(E+P))  -- no overflow, no clamps.
__device__ __forceinline__ float actfn(float y, float P) {
    float E   = __expf(-10.0f * fabsf(y));
    float EP  = E * P;
    float num = fmaf(EP, E, fmaf(2.0f, E, P));
    float den = (1.0f + EP) * (E + P);
    return y * __fdividef(num, den);
}

__global__ void __launch_bounds__(THREADS, 1)
wpt_kernel(const float* __restrict__ x, float* __restrict__ out,
           const float* __restrict__ b1, const float* __restrict__ b2,
           const float* __restrict__ b3, const float* __restrict__ b4,
           const float* __restrict__ b5)
{
    extern __shared__ float Sraw[];
    float* S = Sraw + GUARD;              // S[-GUARD .. SBUF+GUARD) valid
    float* B = Sraw + GUARD + SBUF + GUARD;
    const int tid = threadIdx.x;
    const int row = blockIdx.x;

    // biases -> smem: offsets 0,2,6,14,30
    if (tid < 2)  B[0  + tid] = b1[tid];
    if (tid < 4)  B[2  + tid] = b2[tid];
    if (tid < 8)  B[6  + tid] = b3[tid];
    if (tid < 16) B[14 + tid] = b4[tid];
    if (tid < 32) B[30 + tid] = b5[tid];

    // load x row into swizzled smem (one swizzle calc per float4; the 4
    // consecutive floats never cross a 32-block since p is 4-aligned)
    const float4* x4 = (const float4*)(x + (size_t)row * NTOT);
    #pragma unroll
    for (int i = 0; i < NTOT / 4 / THREADS; ++i) {
        int idx = tid + i * THREADS;
        float4 v = x4[idx];
        int p = 4 * idx;
        int q = p + (p >> 5);
        S[q + 0] = v.x;
        S[q + 1] = v.y;
        S[q + 2] = v.z;
        S[q + 3] = v.w;
    }
    __syncthreads();

    // ---------------- 5 analysis levels (in-place) ----------------
    #pragma unroll 1
    for (int li = 0; li < 5; ++li) {
        const int Nl = NTOT >> li;       // input channel length
        const int M  = Nl >> 1;          // output channel length
        const int pos0 = tid << 5;       // 32 output sites per thread
        const int c  = pos0 >> (14 - li);
        const int m0 = pos0 & (M - 1);   // multiple of 32
        const int base = c * Nl;

        // physical base of (base + 2*m0), which is 32-aligned
        const int a0 = base + 2 * m0;
        const int A  = a0 + (a0 >> 5);

        // stage input window [2m0-3, 2m0+66] with literal offsets
        float xs[70];
        #pragma unroll
        for (int j = 0; j < 70; ++j) {
            int d = j - 3;
            int adj = (d < 0) ? -1 : ((d < 32) ? 0 : ((d < 64) ? 1 : 2));
            xs[j] = S[A + d + adj];
        }
        // halo fixups (only boundary threads of each channel)
        if (m0 == 0)      { xs[0] = 0.f; xs[1] = 0.f; xs[2] = 0.f; }
        if (m0 == M - 32) { xs[67] = 0.f; xs[68] = 0.f; xs[69] = 0.f; }

        const int  bo    = (2 << li) - 2;
        const bool ceven = ((c & 1) == 0);
        const float PA = __expf(10.0f * B[bo + 2 * c]);      // out ch 2c
        const float PB = __expf(10.0f * B[bo + 2 * c + 1]);  // out ch 2c+1

        // physical write bases (32-aligned, k<32 never crosses)
        const int w0 = base + m0;
        const int Wa = w0 + (w0 >> 5);
        const int w1 = base + M + m0;
        const int Wb = w1 + (w1 >> 5);
        __syncthreads();

        #pragma unroll
        for (int k = 0; k < 32; ++k) {
            float lpv =
                fmaf(xs[2*k+0], LP0, fmaf(xs[2*k+1], LP1,
                fmaf(xs[2*k+2], LP2, fmaf(xs[2*k+3], LP3,
                fmaf(xs[2*k+4], LP4, fmaf(xs[2*k+5], LP5,
                fmaf(xs[2*k+6], LP6, xs[2*k+7] * LP7)))))));
            float hpv =
                fmaf(xs[2*k+0], HP0, fmaf(xs[2*k+1], HP1,
                fmaf(xs[2*k+2], HP2, fmaf(xs[2*k+3], HP3,
                fmaf(xs[2*k+4], HP4, fmaf(xs[2*k+5], HP5,
                fmaf(xs[2*k+6], HP6, xs[2*k+7] * HP7)))))));
            float vA = ceven ? lpv : hpv;   // out channel 2c
            float vB = ceven ? hpv : lpv;   // out channel 2c+1
            S[Wa + k] = actfn(vA, PA);
            S[Wb + k] = actfn(vB, PB);
        }
        __syncthreads();
    }

    // ---------------- 5 synthesis levels (in-place) ----------------
    #pragma unroll 1
    for (int li = 4; li >= 0; --li) {
        const int M   = NTOT >> (li + 1); // input channel length; output 2M
        const int n0t = tid << 6;         // 64 outputs per thread
        const int c   = n0t >> (15 - li);
        const int n0  = n0t & (2 * M - 1); // multiple of 64
        const int m0  = n0 >> 1;           // multiple of 32
        const bool ceven = ((c & 1) == 0);
        const int baseL = (2 * c + (ceven ? 0 : 1)) * M;
        const int baseH = (2 * c + (ceven ? 1 : 0)) * M;

        const int l0 = baseL + m0;
        const int PL = l0 + (l0 >> 5);
        const int h0 = baseH + m0;
        const int PH = h0 + (h0 >> 5);

        float yl[36], yh[36];
        #pragma unroll
        for (int j = 0; j < 36; ++j) {
            int d = j - 2;
            int adj = (d < 0) ? -1 : ((d < 32) ? 0 : 1);
            yl[j] = S[PL + d + adj];
            yh[j] = S[PH + d + adj];
        }
        if (m0 == 0) {
            yl[0] = 0.f; yl[1] = 0.f; yh[0] = 0.f; yh[1] = 0.f;
        }
        if (m0 == M - 32) {
            yl[34] = 0.f; yl[35] = 0.f; yh[34] = 0.f; yh[35] = 0.f;
        }

        const int ob = 2 * c * M + n0;     // multiple of 64
        const int W  = ob + (ob >> 5);
        __syncthreads();

        #pragma unroll
        for (int u = 0; u < 32; ++u) {
            // even output n0+2u
            float e =
                fmaf(yl[u+3], LP1, fmaf(yl[u+2], LP3,
                fmaf(yl[u+1], LP5, fmaf(yl[u+0], LP7,
                fmaf(yh[u+3], HP1, fmaf(yh[u+2], HP3,
                fmaf(yh[u+1], HP5, yh[u+0] * HP7)))))));
            // odd output n0+2u+1
            float o =
                fmaf(yl[u+4], LP0, fmaf(yl[u+3], LP2,
                fmaf(yl[u+2], LP4, fmaf(yl[u+1], LP6,
                fmaf(yh[u+4], HP0, fmaf(yh[u+3], HP2,
                fmaf(yh[u+2], HP4, yh[u+1] * HP6)))))));
            int t0 = 2 * u;
            int t1 = 2 * u + 1;
            S[W + t0 + ((t0 >= 32) ? 1 : 0)] = e;
            S[W + t1 + ((t1 >= 32) ? 1 : 0)] = o;
        }
        __syncthreads();
    }

    // store result row
    float4* o4 = (float4*)(out + (size_t)row * NTOT);
    #pragma unroll
    for (int i = 0; i < NTOT / 4 / THREADS; ++i) {
        int idx = tid + i * THREADS;
        int p = 4 * idx;
        int q = p + (p >> 5);
        float4 v;
        v.x = S[q + 0];
        v.y = S[q + 1];
        v.z = S[q + 2];
        v.w = S[q + 3];
        o4[idx] = v;
    }
}

extern "C" void kernel_launch(void* const* d_in, const int* in_sizes, int n_in,
                              void* d_out, int out_size)
{
    const float* x = (const float*)d_in[0];
    for (int i = 0; i < n_in; ++i)
        if (in_sizes[i] == 128 * NTOT) { x = (const float*)d_in[i]; break; }

    // biases have sizes 2,4,8,16,32; k1/k2 collide (16/32) but come earlier,
    // so scan from the END, first match per size wins.
    const float* bs[5] = {nullptr, nullptr, nullptr, nullptr, nullptr};
    for (int i = n_in - 1; i >= 0; --i) {
        int s = in_sizes[i];
        for (int l = 0; l < 5; ++l) {
            if (s == (2 << l) && bs[l] == nullptr) {
                bs[l] = (const float*)d_in[i];
                break;
            }
        }
    }

    cudaFuncSetAttribute(wpt_kernel, cudaFuncAttributeMaxDynamicSharedMemorySize,
                         SMEM_BYTES);

    int rows = out_size / NTOT;
    wpt_kernel<<<rows, THREADS, SMEM_BYTES>>>(
        x, (float*)d_out, bs[0], bs[1], bs[2], bs[3], bs[4]);
}

// round 7
// speedup vs baseline: 1.6190x; 1.1033x over previous
#include <cuda_runtime.h>

#define NTOT 32768
#define THREADS 1024
#define SBUF 33808            // >= sw(NTOT) + top halo margin
#define GUARD 8
#define SMEM_FLOATS (GUARD + SBUF + GUARD + 64)
#define SMEM_BYTES (SMEM_FLOATS * 4)

// db4 lowpass taps
#define LP0 (-0.010597401784997278f)
#define LP1 ( 0.032883011666982945f)
#define LP2 ( 0.030841381835986965f)
#define LP3 (-0.18703481171888114f)
#define LP4 (-0.02798376941698385f)
#define LP5 ( 0.6308807679295904f)
#define LP6 ( 0.7148465705525415f)
#define LP7 ( 0.23037781330885523f)
// hp[t] = lp[7-t] * (-1)^t
#define HP0 ( LP7)
#define HP1 (-LP6)
#define HP2 ( LP5)
#define HP3 (-LP4)
#define HP4 ( LP3)
#define HP5 (-LP2)
#define HP6 ( LP1)
#define HP7 (-LP0)

// gate(y,b) = sigmoid(10(y-b)) + sigmoid(-10(y+b)) is even in y.
// With z=|y|, E=e^{-10z} in (0,1], P=e^{10b} in [1,e]:
// gate = (2E + P + E*E*P) / ((1+E*P)*(E+P))  -- no overflow, no clamps.
__device__ __forceinline__ float actfn(float y, float P) {
    float E   = __expf(-10.0f * fabsf(y));
    float EP  = E * P;
    float num = fmaf(EP, E, fmaf(2.0f, E, P));
    float den = (1.0f + EP) * (E + P);
    return y * __fdividef(num, den);
}

__global__ void __launch_bounds__(THREADS, 1)
wpt_kernel(const float* __restrict__ x, float* __restrict__ out,
           const float* __restrict__ b1, const float* __restrict__ b2,
           const float* __restrict__ b3, const float* __restrict__ b4,
           const float* __restrict__ b5)
{
    extern __shared__ float Sraw[];
    float* S = Sraw + GUARD;              // S[-GUARD .. SBUF+GUARD) valid
    float* B = Sraw + GUARD + SBUF + GUARD;
    const int tid = threadIdx.x;
    const int row = blockIdx.x;

    // biases -> smem: offsets 0,2,6,14,30
    if (tid < 2)  B[0  + tid] = b1[tid];
    if (tid < 4)  B[2  + tid] = b2[tid];
    if (tid < 8)  B[6  + tid] = b3[tid];
    if (tid < 16) B[14 + tid] = b4[tid];
    if (tid < 32) B[30 + tid] = b5[tid];

    // load x row into swizzled smem
    const float4* x4 = (const float4*)(x + (size_t)row * NTOT);
    #pragma unroll
    for (int i = 0; i < NTOT / 4 / THREADS; ++i) {
        int idx = tid + i * THREADS;
        float4 v = x4[idx];
        int p = 4 * idx;
        int q = p + (p >> 5);
        S[q + 0] = v.x;
        S[q + 1] = v.y;
        S[q + 2] = v.z;
        S[q + 3] = v.w;
    }
    __syncthreads();

    // ---------------- 5 analysis levels (in-place) ----------------
    #pragma unroll 1
    for (int li = 0; li < 5; ++li) {
        const int Nl = NTOT >> li;       // input channel length
        const int M  = Nl >> 1;          // output channel length
        const int pos0 = tid << 4;       // 16 output sites per thread
        const int c  = pos0 >> (14 - li);
        const int m0 = pos0 & (M - 1);   // multiple of 16
        const int base = c * Nl;         // multiple of 2048

        // physical base of (base + 2*m0): 32-aligned
        const int a0 = base + 2 * m0;
        const int A  = a0 + (a0 >> 5);

        // stage input window [2m0-3, 2m0+34] with literal offsets
        // (A is 32-block aligned: d<0 -> prev block, d in [32,34] -> next)
        float xs[38];
        #pragma unroll
        for (int j = 0; j < 38; ++j) {
            int d = j - 3;
            int adj = (d < 0) ? -1 : ((d < 32) ? 0 : 1);
            xs[j] = S[A + d + adj];
        }
        // halo fixups (boundary threads of each channel only)
        if (m0 == 0)      { xs[0] = 0.f; xs[1] = 0.f; xs[2] = 0.f; }
        if (m0 == M - 16) { xs[35] = 0.f; xs[36] = 0.f; xs[37] = 0.f; }

        const int  bo    = (2 << li) - 2;
        const bool ceven = ((c & 1) == 0);
        const float PA = __expf(10.0f * B[bo + 2 * c]);      // out ch 2c
        const float PB = __expf(10.0f * B[bo + 2 * c + 1]);  // out ch 2c+1

        // physical write bases; 16-float runs from a 16-aligned logical base
        // never cross a 32-block, so one swizzle each suffices
        const int w0 = base + m0;
        const int Wa = w0 + (w0 >> 5);
        const int w1 = base + M + m0;
        const int Wb = w1 + (w1 >> 5);
        // out ch 2c carries lpv when c even, hpv when c odd
        const int   Wlp = ceven ? Wa : Wb;
        const int   Whp = ceven ? Wb : Wa;
        const float Plp = ceven ? PA : PB;
        const float Php = ceven ? PB : PA;
        __syncthreads();

        #pragma unroll
        for (int k = 0; k < 16; ++k) {
            float lpv =
                fmaf(xs[2*k+0], LP0, fmaf(xs[2*k+1], LP1,
                fmaf(xs[2*k+2], LP2, fmaf(xs[2*k+3], LP3,
                fmaf(xs[2*k+4], LP4, fmaf(xs[2*k+5], LP5,
                fmaf(xs[2*k+6], LP6, xs[2*k+7] * LP7)))))));
            float hpv =
                fmaf(xs[2*k+0], HP0, fmaf(xs[2*k+1], HP1,
                fmaf(xs[2*k+2], HP2, fmaf(xs[2*k+3], HP3,
                fmaf(xs[2*k+4], HP4, fmaf(xs[2*k+5], HP5,
                fmaf(xs[2*k+6], HP6, xs[2*k+7] * HP7)))))));
            S[Wlp + k] = actfn(lpv, Plp);
            S[Whp + k] = actfn(hpv, Php);
        }
        __syncthreads();
    }

    // ---------------- 5 synthesis levels (in-place) ----------------
    #pragma unroll 1
    for (int li = 4; li >= 0; --li) {
        const int M   = NTOT >> (li + 1); // input channel length; output 2M
        const int n0t = tid << 5;         // 32 outputs per thread
        const int c   = n0t >> (15 - li);
        const int n0  = n0t & (2 * M - 1); // multiple of 32
        const int m0  = n0 >> 1;           // multiple of 16 ONLY
        const bool ceven = ((c & 1) == 0);
        const int baseL = (2 * c + (ceven ? 0 : 1)) * M;  // multiple of 512
        const int baseH = (2 * c + (ceven ? 1 : 0)) * M;

        // l0/h0 are congruent to m0 (mod 32); par=1 means block boundary at d=16
        const int par = (m0 >> 4) & 1;
        const int adj_neg = par ? 0 : -1;  // for d in [-2, 0)
        const int adj_hi  = par;           // for d in [16, 18)

        const int l0 = baseL + m0;
        const int PL  = l0 + (l0 >> 5);
        const int PLn = PL + adj_neg;
        const int PLh = PL + adj_hi;
        const int h0 = baseH + m0;
        const int PH  = h0 + (h0 >> 5);
        const int PHn = PH + adj_neg;
        const int PHh = PH + adj_hi;

        // stage [m0-2, m0+17] from both channels; d = j-2
        float yl[20], yh[20];
        yl[0] = S[PLn - 2];  yl[1] = S[PLn - 1];
        yh[0] = S[PHn - 2];  yh[1] = S[PHn - 1];
        #pragma unroll
        for (int j = 2; j < 18; ++j) {   // d in [0,16)
            yl[j] = S[PL + j - 2];
            yh[j] = S[PH + j - 2];
        }
        yl[18] = S[PLh + 16]; yl[19] = S[PLh + 17];
        yh[18] = S[PHh + 16]; yh[19] = S[PHh + 17];

        if (m0 == 0) {
            yl[0] = 0.f; yl[1] = 0.f; yh[0] = 0.f; yh[1] = 0.f;
        }
        if (m0 == M - 16) {
            yl[18] = 0.f; yl[19] = 0.f; yh[18] = 0.f; yh[19] = 0.f;
        }

        const int ob = 2 * c * M + n0;     // multiple of 32
        const int W  = ob + (ob >> 5);     // t<32 never crosses a 32-block
        __syncthreads();

        #pragma unroll
        for (int u = 0; u < 16; ++u) {
            // even output n0+2u
            float e =
                fmaf(yl[u+3], LP1, fmaf(yl[u+2], LP3,
                fmaf(yl[u+1], LP5, fmaf(yl[u+0], LP7,
                fmaf(yh[u+3], HP1, fmaf(yh[u+2], HP3,
                fmaf(yh[u+1], HP5, yh[u+0] * HP7)))))));
            // odd output n0+2u+1
            float o =
                fmaf(yl[u+4], LP0, fmaf(yl[u+3], LP2,
                fmaf(yl[u+2], LP4, fmaf(yl[u+1], LP6,
                fmaf(yh[u+4], HP0, fmaf(yh[u+3], HP2,
                fmaf(yh[u+2], HP4, yh[u+1] * HP6)))))));
            S[W + 2*u]     = e;
            S[W + 2*u + 1] = o;
        }
        __syncthreads();
    }

    // store result row
    float4* o4 = (float4*)(out + (size_t)row * NTOT);
    #pragma unroll
    for (int i = 0; i < NTOT / 4 / THREADS; ++i) {
        int idx = tid + i * THREADS;
        int p = 4 * idx;
        int q = p + (p >> 5);
        float4 v;
        v.x = S[q + 0];
        v.y = S[q + 1];
        v.z = S[q + 2];
        v.w = S[q + 3];
        o4[idx] = v;
    }
}

extern "C" void kernel_launch(void* const* d_in, const int* in_sizes, int n_in,
                              void* d_out, int out_size)
{
    const float* x = (const float*)d_in[0];
    for (int i = 0; i < n_in; ++i)
        if (in_sizes[i] == 128 * NTOT) { x = (const float*)d_in[i]; break; }

    // biases have sizes 2,4,8,16,32; k1/k2 collide (16/32) but come earlier,
    // so scan from the END, first match per size wins.
    const float* bs[5] = {nullptr, nullptr, nullptr, nullptr, nullptr};
    for (int i = n_in - 1; i >= 0; --i) {
        int s = in_sizes[i];
        for (int l = 0; l < 5; ++l) {
            if (s == (2 << l) && bs[l] == nullptr) {
                bs[l] = (const float*)d_in[i];
                break;
            }
        }
    }

    cudaFuncSetAttribute(wpt_kernel, cudaFuncAttributeMaxDynamicSharedMemorySize,
                         SMEM_BYTES);

    int rows = out_size / NTOT;
    wpt_kernel<<<rows, THREADS, SMEM_BYTES>>>(
        x, (float*)d_out, bs[0], bs[1], bs[2], bs[3], bs[4]);
}